// round 10
// baseline (speedup 1.0000x reference)
#include <cuda_runtime.h>
#include <cstdint>

// LSTM: IN=14, H=28, OUT=2, B=4096, T=512
// Round-1 structure (one warp per sequence, all weights register-resident,
// packed fma.rn.f32x2) + two schedule fixes:
//  1) Software pipelining: x-part accumulators for step t+1 (independent of
//     h_t) are computed interleaved with step t's activation tail, so the
//     warp's own FFMA2s fill the MUFU/LDS latency shadows.
//  2) Double-buffered h exchange -> single __syncwarp per step.
// No launch_bounds cap (round-5 lesson: caps below ~235 regs spill weights).

#define IN_DIM 14
#define HID    28
#define TSTEPS 512
#define BATCH  4096

typedef unsigned long long u64;

__device__ __forceinline__ u64 pack2(float lo, float hi) {
    u64 r; asm("mov.b64 %0, {%1, %2};" : "=l"(r) : "f"(lo), "f"(hi)); return r;
}
__device__ __forceinline__ void unpack2(u64 v, float& lo, float& hi) {
    asm("mov.b64 {%0, %1}, %2;" : "=f"(lo), "=f"(hi) : "l"(v));
}
__device__ __forceinline__ void ffma2(u64& acc, u64 a, u64 b) {
    asm("fma.rn.f32x2 %0, %1, %2, %0;" : "+l"(acc) : "l"(a), "l"(b));
}
__device__ __forceinline__ float fast_ex2(float x) {
    float r; asm("ex2.approx.f32 %0, %1;" : "=f"(r) : "f"(x)); return r;
}
__device__ __forceinline__ float fast_rcp(float x) {
    float r; asm("rcp.approx.f32 %0, %1;" : "=f"(r) : "f"(x)); return r;
}
__device__ __forceinline__ float sigm(float x) {
    return fast_rcp(1.0f + fast_ex2(-1.4426950408889634f * x));
}
__device__ __forceinline__ float tanh_f(float x) {
    return fmaf(2.0f, fast_rcp(1.0f + fast_ex2(-2.8853900817779268f * x)), -1.0f);
}

__global__ void __launch_bounds__(32)
lstm_kernel(const float* __restrict__ x,
            const float* __restrict__ W_ih,
            const float* __restrict__ W_hh,
            const float* __restrict__ b_ih,
            const float* __restrict__ b_hh,
            const float* __restrict__ W_out,
            const float* __restrict__ b_out,
            float* __restrict__ out)
{
    const int seq  = blockIdx.x;            // 4096 blocks = 4096 sequences
    const int lane = threadIdx.x;
    const int j    = (lane < HID) ? lane : (HID - 1);

    // ---- register-resident weights (f32x2 pairs over k) ----
    u64 wih[4][IN_DIM / 2];   // 56 regs
    u64 whh[4][HID / 2];      // 112 regs
    u64 bias[4];
#pragma unroll
    for (int g = 0; g < 4; g++) {
        const int r = g * HID + j;
        const u64* wi = (const u64*)(W_ih + r * IN_DIM);
#pragma unroll
        for (int p = 0; p < IN_DIM / 2; p++) wih[g][p] = wi[p];
        const u64* wh = (const u64*)(W_hh + r * HID);
#pragma unroll
        for (int p = 0; p < HID / 2; p++) whh[g][p] = wh[p];
        bias[g] = pack2(b_ih[r] + b_hh[r], 0.0f);
    }

    // double-buffered h exchange: write buf (t+1)&1, read buf t&1
    __shared__ __align__(16) float hs[2][32];
    hs[0][lane] = 0.0f;
    float h = 0.0f, c = 0.0f;

    const u64* xq = (const u64*)(x + (size_t)seq * TSTEPS * IN_DIM);
    u64 xc[7];                 // x pairs for step t+1 (for computing Bx)
#pragma unroll
    for (int p = 0; p < 7; p++) xc[p] = xq[p];

    // Ax = bias + x(0)*W_ih  (x-part accumulators carried across iterations)
    u64 Ax0 = bias[0], Ax1 = bias[1], Ax2 = bias[2], Ax3 = bias[3];
#pragma unroll
    for (int p = 0; p < 7; p++) {
        ffma2(Ax0, wih[0][p], xc[p]);
        ffma2(Ax1, wih[1][p], xc[p]);
        ffma2(Ax2, wih[2][p], xc[p]);
        ffma2(Ax3, wih[3][p], xc[p]);
    }
#pragma unroll
    for (int p = 0; p < 7; p++) xc[p] = xq[7 + p];   // x(1)
    __syncwarp();

#pragma unroll 1
    for (int t = 0; t < TSTEPS; t++) {
        // ---- h-part: A = Ax + h(t)-contributions (56 FFMA2, LDS broadcast) ----
        u64 A0 = Ax0, A1 = Ax1, A2 = Ax2, A3 = Ax3;
        const float* hb = hs[t & 1];
#pragma unroll
        for (int q = 0; q < HID / 2; q++) {
            const u64 hv = *(const u64*)(hb + 2 * q);   // LDS.64 broadcast
            ffma2(A0, whh[0][q], hv);
            ffma2(A1, whh[1][q], hv);
            ffma2(A2, whh[2][q], hv);
            ffma2(A3, whh[3][q], hv);
        }

        float lo, hi;
        unpack2(A0, lo, hi); const float gi = lo + hi;
        unpack2(A1, lo, hi); const float gf = lo + hi;
        unpack2(A2, lo, hi); const float gg = lo + hi;
        unpack2(A3, lo, hi); const float go = lo + hi;

        // ---- x-part for step t+1 (independent of h_t: fills MUFU shadows) ----
        u64 Bx0 = bias[0], Bx1 = bias[1], Bx2 = bias[2], Bx3 = bias[3];
#pragma unroll
        for (int p = 0; p < 7; p++) {
            ffma2(Bx0, wih[0][p], xc[p]);
            ffma2(Bx1, wih[1][p], xc[p]);
            ffma2(Bx2, wih[2][p], xc[p]);
            ffma2(Bx3, wih[3][p], xc[p]);
        }

        // ---- activation tail (interleaved with Bx by ptxas) ----
        const float ia = sigm(gi);
        const float fa = sigm(gf);
        const float ga = tanh_f(gg);
        const float oa = sigm(go);
        c = fmaf(fa, c, ia * ga);
        h = oa * tanh_f(c);

        // prefetch x(t+2) pairs
        {
            const int t2 = (t + 2 < TSTEPS) ? (t + 2) : (TSTEPS - 1);
            const u64* xr = xq + t2 * 7;
#pragma unroll
            for (int p = 0; p < 7; p++) xc[p] = xr[p];
        }

        hs[(t + 1) & 1][lane] = h;
        __syncwarp();            // writes visible; also orders next iter's
                                 // overwrite of buf t&1 after this iter's reads

        Ax0 = Bx0; Ax1 = Bx1; Ax2 = Bx2; Ax3 = Bx3;
    }

    // out[seq, o] = sum_j h_j * W_out[o, j] + b_out[o]
    const bool act = (lane < HID);
    const float w0 = act ? W_out[lane]       : 0.0f;
    const float w1 = act ? W_out[HID + lane] : 0.0f;
    float v0 = act ? h * w0 : 0.0f;
    float v1 = act ? h * w1 : 0.0f;
#pragma unroll
    for (int off = 16; off; off >>= 1) {
        v0 += __shfl_down_sync(0xffffffffu, v0, off);
        v1 += __shfl_down_sync(0xffffffffu, v1, off);
    }
    if (lane == 0) {
        out[seq * 2 + 0] = v0 + b_out[0];
        out[seq * 2 + 1] = v1 + b_out[1];
    }
}

extern "C" void kernel_launch(void* const* d_in, const int* in_sizes, int n_in,
                              void* d_out, int out_size)
{
    const float* x     = (const float*)d_in[0];
    const float* W_ih  = (const float*)d_in[1];
    const float* W_hh  = (const float*)d_in[2];
    const float* b_ih  = (const float*)d_in[3];
    const float* b_hh  = (const float*)d_in[4];
    const float* W_out = (const float*)d_in[5];
    const float* b_out = (const float*)d_in[6];
    float* out = (float*)d_out;

    lstm_kernel<<<BATCH, 32>>>(x, W_ih, W_hh, b_ih, b_hh, W_out, b_out, out);
}

// round 11
// speedup vs baseline: 1.4433x; 1.4433x over previous
#include <cuda_runtime.h>
#include <cstdint>

// LSTM: IN=14, H=28, OUT=2, B=4096, T=512
// Round-1 structure (one warp per sequence, all weights register-resident,
// packed fma.rn.f32x2) + two schedule fixes:
//  1) Software pipelining: x-part accumulators for step t+1 (independent of
//     h_t) are computed interleaved with step t's activation tail, so the
//     warp's own FFMA2s fill the MUFU/LDS latency shadows.
//  2) Double-buffered h exchange -> single __syncwarp per step.
// No launch_bounds cap (round-5 lesson: caps below ~235 regs spill weights).

#define IN_DIM 14
#define HID    28
#define TSTEPS 512
#define BATCH  4096

typedef unsigned long long u64;

__device__ __forceinline__ u64 pack2(float lo, float hi) {
    u64 r; asm("mov.b64 %0, {%1, %2};" : "=l"(r) : "f"(lo), "f"(hi)); return r;
}
__device__ __forceinline__ void unpack2(u64 v, float& lo, float& hi) {
    asm("mov.b64 {%0, %1}, %2;" : "=f"(lo), "=f"(hi) : "l"(v));
}
__device__ __forceinline__ void ffma2(u64& acc, u64 a, u64 b) {
    asm("fma.rn.f32x2 %0, %1, %2, %0;" : "+l"(acc) : "l"(a), "l"(b));
}
__device__ __forceinline__ float fast_ex2(float x) {
    float r; asm("ex2.approx.f32 %0, %1;" : "=f"(r) : "f"(x)); return r;
}
__device__ __forceinline__ float fast_rcp(float x) {
    float r; asm("rcp.approx.f32 %0, %1;" : "=f"(r) : "f"(x)); return r;
}
__device__ __forceinline__ float sigm(float x) {
    return fast_rcp(1.0f + fast_ex2(-1.4426950408889634f * x));
}
__device__ __forceinline__ float tanh_f(float x) {
    return fmaf(2.0f, fast_rcp(1.0f + fast_ex2(-2.8853900817779268f * x)), -1.0f);
}

__global__ void __launch_bounds__(32)
lstm_kernel(const float* __restrict__ x,
            const float* __restrict__ W_ih,
            const float* __restrict__ W_hh,
            const float* __restrict__ b_ih,
            const float* __restrict__ b_hh,
            const float* __restrict__ W_out,
            const float* __restrict__ b_out,
            float* __restrict__ out)
{
    const int seq  = blockIdx.x;            // 4096 blocks = 4096 sequences
    const int lane = threadIdx.x;
    const int j    = (lane < HID) ? lane : (HID - 1);

    // ---- register-resident weights (f32x2 pairs over k) ----
    u64 wih[4][IN_DIM / 2];   // 56 regs
    u64 whh[4][HID / 2];      // 112 regs
    u64 bias[4];
#pragma unroll
    for (int g = 0; g < 4; g++) {
        const int r = g * HID + j;
        const u64* wi = (const u64*)(W_ih + r * IN_DIM);
#pragma unroll
        for (int p = 0; p < IN_DIM / 2; p++) wih[g][p] = wi[p];
        const u64* wh = (const u64*)(W_hh + r * HID);
#pragma unroll
        for (int p = 0; p < HID / 2; p++) whh[g][p] = wh[p];
        bias[g] = pack2(b_ih[r] + b_hh[r], 0.0f);
    }

    // double-buffered h exchange: write buf (t+1)&1, read buf t&1
    __shared__ __align__(16) float hs[2][32];
    hs[0][lane] = 0.0f;
    float h = 0.0f, c = 0.0f;

    const u64* xq = (const u64*)(x + (size_t)seq * TSTEPS * IN_DIM);
    u64 xc[7];                 // x pairs for step t+1 (for computing Bx)
#pragma unroll
    for (int p = 0; p < 7; p++) xc[p] = xq[p];

    // Ax = bias + x(0)*W_ih  (x-part accumulators carried across iterations)
    u64 Ax0 = bias[0], Ax1 = bias[1], Ax2 = bias[2], Ax3 = bias[3];
#pragma unroll
    for (int p = 0; p < 7; p++) {
        ffma2(Ax0, wih[0][p], xc[p]);
        ffma2(Ax1, wih[1][p], xc[p]);
        ffma2(Ax2, wih[2][p], xc[p]);
        ffma2(Ax3, wih[3][p], xc[p]);
    }
#pragma unroll
    for (int p = 0; p < 7; p++) xc[p] = xq[7 + p];   // x(1)
    __syncwarp();

#pragma unroll 1
    for (int t = 0; t < TSTEPS; t++) {
        // ---- h-part: A = Ax + h(t)-contributions (56 FFMA2, LDS broadcast) ----
        u64 A0 = Ax0, A1 = Ax1, A2 = Ax2, A3 = Ax3;
        const float* hb = hs[t & 1];
#pragma unroll
        for (int q = 0; q < HID / 2; q++) {
            const u64 hv = *(const u64*)(hb + 2 * q);   // LDS.64 broadcast
            ffma2(A0, whh[0][q], hv);
            ffma2(A1, whh[1][q], hv);
            ffma2(A2, whh[2][q], hv);
            ffma2(A3, whh[3][q], hv);
        }

        float lo, hi;
        unpack2(A0, lo, hi); const float gi = lo + hi;
        unpack2(A1, lo, hi); const float gf = lo + hi;
        unpack2(A2, lo, hi); const float gg = lo + hi;
        unpack2(A3, lo, hi); const float go = lo + hi;

        // ---- x-part for step t+1 (independent of h_t: fills MUFU shadows) ----
        u64 Bx0 = bias[0], Bx1 = bias[1], Bx2 = bias[2], Bx3 = bias[3];
#pragma unroll
        for (int p = 0; p < 7; p++) {
            ffma2(Bx0, wih[0][p], xc[p]);
            ffma2(Bx1, wih[1][p], xc[p]);
            ffma2(Bx2, wih[2][p], xc[p]);
            ffma2(Bx3, wih[3][p], xc[p]);
        }

        // ---- activation tail (interleaved with Bx by ptxas) ----
        const float ia = sigm(gi);
        const float fa = sigm(gf);
        const float ga = tanh_f(gg);
        const float oa = sigm(go);
        c = fmaf(fa, c, ia * ga);
        h = oa * tanh_f(c);

        // prefetch x(t+2) pairs
        {
            const int t2 = (t + 2 < TSTEPS) ? (t + 2) : (TSTEPS - 1);
            const u64* xr = xq + t2 * 7;
#pragma unroll
            for (int p = 0; p < 7; p++) xc[p] = xr[p];
        }

        hs[(t + 1) & 1][lane] = h;
        __syncwarp();            // writes visible; also orders next iter's
                                 // overwrite of buf t&1 after this iter's reads

        Ax0 = Bx0; Ax1 = Bx1; Ax2 = Bx2; Ax3 = Bx3;
    }

    // out[seq, o] = sum_j h_j * W_out[o, j] + b_out[o]
    const bool act = (lane < HID);
    const float w0 = act ? W_out[lane]       : 0.0f;
    const float w1 = act ? W_out[HID + lane] : 0.0f;
    float v0 = act ? h * w0 : 0.0f;
    float v1 = act ? h * w1 : 0.0f;
#pragma unroll
    for (int off = 16; off; off >>= 1) {
        v0 += __shfl_down_sync(0xffffffffu, v0, off);
        v1 += __shfl_down_sync(0xffffffffu, v1, off);
    }
    if (lane == 0) {
        out[seq * 2 + 0] = v0 + b_out[0];
        out[seq * 2 + 1] = v1 + b_out[1];
    }
}

extern "C" void kernel_launch(void* const* d_in, const int* in_sizes, int n_in,
                              void* d_out, int out_size)
{
    const float* x     = (const float*)d_in[0];
    const float* W_ih  = (const float*)d_in[1];
    const float* W_hh  = (const float*)d_in[2];
    const float* b_ih  = (const float*)d_in[3];
    const float* b_hh  = (const float*)d_in[4];
    const float* W_out = (const float*)d_in[5];
    const float* b_out = (const float*)d_in[6];
    float* out = (float*)d_out;

    lstm_kernel<<<BATCH, 32>>>(x, W_ih, W_hh, b_ih, b_hh, W_out, b_out, out);
}

// round 12
// speedup vs baseline: 1.4615x; 1.0126x over previous
#include <cuda_runtime.h>
#include <cstdint>

// LSTM: IN=14, H=28, OUT=2, B=4096, T=512
// Round-1 structure (one warp per sequence, all weights register-resident,
// packed fma.rn.f32x2) + two schedule fixes:
//  1) Software pipelining: x-part accumulators for step t+1 (independent of
//     h_t) are computed interleaved with step t's activation tail, so the
//     warp's own FFMA2s fill the MUFU/LDS latency shadows.
//  2) Double-buffered h exchange -> single __syncwarp per step.
// No launch_bounds cap (round-5 lesson: caps below ~235 regs spill weights).

#define IN_DIM 14
#define HID    28
#define TSTEPS 512
#define BATCH  4096

typedef unsigned long long u64;

__device__ __forceinline__ u64 pack2(float lo, float hi) {
    u64 r; asm("mov.b64 %0, {%1, %2};" : "=l"(r) : "f"(lo), "f"(hi)); return r;
}
__device__ __forceinline__ void unpack2(u64 v, float& lo, float& hi) {
    asm("mov.b64 {%0, %1}, %2;" : "=f"(lo), "=f"(hi) : "l"(v));
}
__device__ __forceinline__ void ffma2(u64& acc, u64 a, u64 b) {
    asm("fma.rn.f32x2 %0, %1, %2, %0;" : "+l"(acc) : "l"(a), "l"(b));
}
__device__ __forceinline__ float fast_ex2(float x) {
    float r; asm("ex2.approx.f32 %0, %1;" : "=f"(r) : "f"(x)); return r;
}
__device__ __forceinline__ float fast_rcp(float x) {
    float r; asm("rcp.approx.f32 %0, %1;" : "=f"(r) : "f"(x)); return r;
}
__device__ __forceinline__ float sigm(float x) {
    return fast_rcp(1.0f + fast_ex2(-1.4426950408889634f * x));
}
__device__ __forceinline__ float tanh_f(float x) {
    return fmaf(2.0f, fast_rcp(1.0f + fast_ex2(-2.8853900817779268f * x)), -1.0f);
}

__global__ void __launch_bounds__(32)
lstm_kernel(const float* __restrict__ x,
            const float* __restrict__ W_ih,
            const float* __restrict__ W_hh,
            const float* __restrict__ b_ih,
            const float* __restrict__ b_hh,
            const float* __restrict__ W_out,
            const float* __restrict__ b_out,
            float* __restrict__ out)
{
    const int seq  = blockIdx.x;            // 4096 blocks = 4096 sequences
    const int lane = threadIdx.x;
    const int j    = (lane < HID) ? lane : (HID - 1);

    // ---- register-resident weights (f32x2 pairs over k) ----
    u64 wih[4][IN_DIM / 2];   // 56 regs
    u64 whh[4][HID / 2];      // 112 regs
    u64 bias[4];
#pragma unroll
    for (int g = 0; g < 4; g++) {
        const int r = g * HID + j;
        const u64* wi = (const u64*)(W_ih + r * IN_DIM);
#pragma unroll
        for (int p = 0; p < IN_DIM / 2; p++) wih[g][p] = wi[p];
        const u64* wh = (const u64*)(W_hh + r * HID);
#pragma unroll
        for (int p = 0; p < HID / 2; p++) whh[g][p] = wh[p];
        bias[g] = pack2(b_ih[r] + b_hh[r], 0.0f);
    }

    // double-buffered h exchange: write buf (t+1)&1, read buf t&1
    __shared__ __align__(16) float hs[2][32];
    hs[0][lane] = 0.0f;
    float h = 0.0f, c = 0.0f;

    const u64* xq = (const u64*)(x + (size_t)seq * TSTEPS * IN_DIM);
    u64 xc[7];                 // x pairs for step t+1 (for computing Bx)
#pragma unroll
    for (int p = 0; p < 7; p++) xc[p] = xq[p];

    // Ax = bias + x(0)*W_ih  (x-part accumulators carried across iterations)
    u64 Ax0 = bias[0], Ax1 = bias[1], Ax2 = bias[2], Ax3 = bias[3];
#pragma unroll
    for (int p = 0; p < 7; p++) {
        ffma2(Ax0, wih[0][p], xc[p]);
        ffma2(Ax1, wih[1][p], xc[p]);
        ffma2(Ax2, wih[2][p], xc[p]);
        ffma2(Ax3, wih[3][p], xc[p]);
    }
#pragma unroll
    for (int p = 0; p < 7; p++) xc[p] = xq[7 + p];   // x(1)
    __syncwarp();

#pragma unroll 1
    for (int t = 0; t < TSTEPS; t++) {
        // ---- h-part: A = Ax + h(t)-contributions (56 FFMA2, LDS broadcast) ----
        u64 A0 = Ax0, A1 = Ax1, A2 = Ax2, A3 = Ax3;
        const float* hb = hs[t & 1];
#pragma unroll
        for (int q = 0; q < HID / 2; q++) {
            const u64 hv = *(const u64*)(hb + 2 * q);   // LDS.64 broadcast
            ffma2(A0, whh[0][q], hv);
            ffma2(A1, whh[1][q], hv);
            ffma2(A2, whh[2][q], hv);
            ffma2(A3, whh[3][q], hv);
        }

        float lo, hi;
        unpack2(A0, lo, hi); const float gi = lo + hi;
        unpack2(A1, lo, hi); const float gf = lo + hi;
        unpack2(A2, lo, hi); const float gg = lo + hi;
        unpack2(A3, lo, hi); const float go = lo + hi;

        // ---- x-part for step t+1 (independent of h_t: fills MUFU shadows) ----
        u64 Bx0 = bias[0], Bx1 = bias[1], Bx2 = bias[2], Bx3 = bias[3];
#pragma unroll
        for (int p = 0; p < 7; p++) {
            ffma2(Bx0, wih[0][p], xc[p]);
            ffma2(Bx1, wih[1][p], xc[p]);
            ffma2(Bx2, wih[2][p], xc[p]);
            ffma2(Bx3, wih[3][p], xc[p]);
        }

        // ---- activation tail (interleaved with Bx by ptxas) ----
        const float ia = sigm(gi);
        const float fa = sigm(gf);
        const float ga = tanh_f(gg);
        const float oa = sigm(go);
        c = fmaf(fa, c, ia * ga);
        h = oa * tanh_f(c);

        // prefetch x(t+2) pairs
        {
            const int t2 = (t + 2 < TSTEPS) ? (t + 2) : (TSTEPS - 1);
            const u64* xr = xq + t2 * 7;
#pragma unroll
            for (int p = 0; p < 7; p++) xc[p] = xr[p];
        }

        hs[(t + 1) & 1][lane] = h;
        __syncwarp();            // writes visible; also orders next iter's
                                 // overwrite of buf t&1 after this iter's reads

        Ax0 = Bx0; Ax1 = Bx1; Ax2 = Bx2; Ax3 = Bx3;
    }

    // out[seq, o] = sum_j h_j * W_out[o, j] + b_out[o]
    const bool act = (lane < HID);
    const float w0 = act ? W_out[lane]       : 0.0f;
    const float w1 = act ? W_out[HID + lane] : 0.0f;
    float v0 = act ? h * w0 : 0.0f;
    float v1 = act ? h * w1 : 0.0f;
#pragma unroll
    for (int off = 16; off; off >>= 1) {
        v0 += __shfl_down_sync(0xffffffffu, v0, off);
        v1 += __shfl_down_sync(0xffffffffu, v1, off);
    }
    if (lane == 0) {
        out[seq * 2 + 0] = v0 + b_out[0];
        out[seq * 2 + 1] = v1 + b_out[1];
    }
}

extern "C" void kernel_launch(void* const* d_in, const int* in_sizes, int n_in,
                              void* d_out, int out_size)
{
    const float* x     = (const float*)d_in[0];
    const float* W_ih  = (const float*)d_in[1];
    const float* W_hh  = (const float*)d_in[2];
    const float* b_ih  = (const float*)d_in[3];
    const float* b_hh  = (const float*)d_in[4];
    const float* W_out = (const float*)d_in[5];
    const float* b_out = (const float*)d_in[6];
    float* out = (float*)d_out;

    lstm_kernel<<<BATCH, 32>>>(x, W_ih, W_hh, b_ih, b_hh, W_out, b_out, out);
}

// round 13
// speedup vs baseline: 1.4616x; 1.0000x over previous
#include <cuda_runtime.h>
#include <cstdint>

// LSTM: IN=14, H=28, OUT=2, B=4096, T=512
// Round-1 structure (one warp per sequence, all weights register-resident,
// packed fma.rn.f32x2) + two schedule fixes:
//  1) Software pipelining: x-part accumulators for step t+1 (independent of
//     h_t) are computed interleaved with step t's activation tail, so the
//     warp's own FFMA2s fill the MUFU/LDS latency shadows.
//  2) Double-buffered h exchange -> single __syncwarp per step.
// No launch_bounds cap (round-5 lesson: caps below ~235 regs spill weights).

#define IN_DIM 14
#define HID    28
#define TSTEPS 512
#define BATCH  4096

typedef unsigned long long u64;

__device__ __forceinline__ u64 pack2(float lo, float hi) {
    u64 r; asm("mov.b64 %0, {%1, %2};" : "=l"(r) : "f"(lo), "f"(hi)); return r;
}
__device__ __forceinline__ void unpack2(u64 v, float& lo, float& hi) {
    asm("mov.b64 {%0, %1}, %2;" : "=f"(lo), "=f"(hi) : "l"(v));
}
__device__ __forceinline__ void ffma2(u64& acc, u64 a, u64 b) {
    asm("fma.rn.f32x2 %0, %1, %2, %0;" : "+l"(acc) : "l"(a), "l"(b));
}
__device__ __forceinline__ float fast_ex2(float x) {
    float r; asm("ex2.approx.f32 %0, %1;" : "=f"(r) : "f"(x)); return r;
}
__device__ __forceinline__ float fast_rcp(float x) {
    float r; asm("rcp.approx.f32 %0, %1;" : "=f"(r) : "f"(x)); return r;
}
__device__ __forceinline__ float sigm(float x) {
    return fast_rcp(1.0f + fast_ex2(-1.4426950408889634f * x));
}
__device__ __forceinline__ float tanh_f(float x) {
    return fmaf(2.0f, fast_rcp(1.0f + fast_ex2(-2.8853900817779268f * x)), -1.0f);
}

__global__ void __launch_bounds__(32)
lstm_kernel(const float* __restrict__ x,
            const float* __restrict__ W_ih,
            const float* __restrict__ W_hh,
            const float* __restrict__ b_ih,
            const float* __restrict__ b_hh,
            const float* __restrict__ W_out,
            const float* __restrict__ b_out,
            float* __restrict__ out)
{
    const int seq  = blockIdx.x;            // 4096 blocks = 4096 sequences
    const int lane = threadIdx.x;
    const int j    = (lane < HID) ? lane : (HID - 1);

    // ---- register-resident weights (f32x2 pairs over k) ----
    u64 wih[4][IN_DIM / 2];   // 56 regs
    u64 whh[4][HID / 2];      // 112 regs
    u64 bias[4];
#pragma unroll
    for (int g = 0; g < 4; g++) {
        const int r = g * HID + j;
        const u64* wi = (const u64*)(W_ih + r * IN_DIM);
#pragma unroll
        for (int p = 0; p < IN_DIM / 2; p++) wih[g][p] = wi[p];
        const u64* wh = (const u64*)(W_hh + r * HID);
#pragma unroll
        for (int p = 0; p < HID / 2; p++) whh[g][p] = wh[p];
        bias[g] = pack2(b_ih[r] + b_hh[r], 0.0f);
    }

    // double-buffered h exchange: write buf (t+1)&1, read buf t&1
    __shared__ __align__(16) float hs[2][32];
    hs[0][lane] = 0.0f;
    float h = 0.0f, c = 0.0f;

    const u64* xq = (const u64*)(x + (size_t)seq * TSTEPS * IN_DIM);
    u64 xc[7];                 // x pairs for step t+1 (for computing Bx)
#pragma unroll
    for (int p = 0; p < 7; p++) xc[p] = xq[p];

    // Ax = bias + x(0)*W_ih  (x-part accumulators carried across iterations)
    u64 Ax0 = bias[0], Ax1 = bias[1], Ax2 = bias[2], Ax3 = bias[3];
#pragma unroll
    for (int p = 0; p < 7; p++) {
        ffma2(Ax0, wih[0][p], xc[p]);
        ffma2(Ax1, wih[1][p], xc[p]);
        ffma2(Ax2, wih[2][p], xc[p]);
        ffma2(Ax3, wih[3][p], xc[p]);
    }
#pragma unroll
    for (int p = 0; p < 7; p++) xc[p] = xq[7 + p];   // x(1)
    __syncwarp();

#pragma unroll 1
    for (int t = 0; t < TSTEPS; t++) {
        // ---- h-part: A = Ax + h(t)-contributions (56 FFMA2, LDS broadcast) ----
        u64 A0 = Ax0, A1 = Ax1, A2 = Ax2, A3 = Ax3;
        const float* hb = hs[t & 1];
#pragma unroll
        for (int q = 0; q < HID / 2; q++) {
            const u64 hv = *(const u64*)(hb + 2 * q);   // LDS.64 broadcast
            ffma2(A0, whh[0][q], hv);
            ffma2(A1, whh[1][q], hv);
            ffma2(A2, whh[2][q], hv);
            ffma2(A3, whh[3][q], hv);
        }

        float lo, hi;
        unpack2(A0, lo, hi); const float gi = lo + hi;
        unpack2(A1, lo, hi); const float gf = lo + hi;
        unpack2(A2, lo, hi); const float gg = lo + hi;
        unpack2(A3, lo, hi); const float go = lo + hi;

        // ---- x-part for step t+1 (independent of h_t: fills MUFU shadows) ----
        u64 Bx0 = bias[0], Bx1 = bias[1], Bx2 = bias[2], Bx3 = bias[3];
#pragma unroll
        for (int p = 0; p < 7; p++) {
            ffma2(Bx0, wih[0][p], xc[p]);
            ffma2(Bx1, wih[1][p], xc[p]);
            ffma2(Bx2, wih[2][p], xc[p]);
            ffma2(Bx3, wih[3][p], xc[p]);
        }

        // ---- activation tail (interleaved with Bx by ptxas) ----
        const float ia = sigm(gi);
        const float fa = sigm(gf);
        const float ga = tanh_f(gg);
        const float oa = sigm(go);
        c = fmaf(fa, c, ia * ga);
        h = oa * tanh_f(c);

        // prefetch x(t+2) pairs
        {
            const int t2 = (t + 2 < TSTEPS) ? (t + 2) : (TSTEPS - 1);
            const u64* xr = xq + t2 * 7;
#pragma unroll
            for (int p = 0; p < 7; p++) xc[p] = xr[p];
        }

        hs[(t + 1) & 1][lane] = h;
        __syncwarp();            // writes visible; also orders next iter's
                                 // overwrite of buf t&1 after this iter's reads

        Ax0 = Bx0; Ax1 = Bx1; Ax2 = Bx2; Ax3 = Bx3;
    }

    // out[seq, o] = sum_j h_j * W_out[o, j] + b_out[o]
    const bool act = (lane < HID);
    const float w0 = act ? W_out[lane]       : 0.0f;
    const float w1 = act ? W_out[HID + lane] : 0.0f;
    float v0 = act ? h * w0 : 0.0f;
    float v1 = act ? h * w1 : 0.0f;
#pragma unroll
    for (int off = 16; off; off >>= 1) {
        v0 += __shfl_down_sync(0xffffffffu, v0, off);
        v1 += __shfl_down_sync(0xffffffffu, v1, off);
    }
    if (lane == 0) {
        out[seq * 2 + 0] = v0 + b_out[0];
        out[seq * 2 + 1] = v1 + b_out[1];
    }
}

extern "C" void kernel_launch(void* const* d_in, const int* in_sizes, int n_in,
                              void* d_out, int out_size)
{
    const float* x     = (const float*)d_in[0];
    const float* W_ih  = (const float*)d_in[1];
    const float* W_hh  = (const float*)d_in[2];
    const float* b_ih  = (const float*)d_in[3];
    const float* b_hh  = (const float*)d_in[4];
    const float* W_out = (const float*)d_in[5];
    const float* b_out = (const float*)d_in[6];
    float* out = (float*)d_out;

    lstm_kernel<<<BATCH, 32>>>(x, W_ih, W_hh, b_ih, b_hh, W_out, b_out, out);
}